// round 1
// baseline (speedup 1.0000x reference)
#include <cuda_runtime.h>
#include <cuda_bf16.h>

// ---------------- problem constants ----------------
#define B_SZ    4
#define LSEQ    2048
#define DMODEL  1024
#define DINNER  2048
#define DSTATE  16
#define DCONV   4
#define NROWS   (B_SZ * LSEQ)           // 8192

// ---------------- scratch (device globals; no allocation allowed) ----------------
__device__ float g_xn [NROWS * DMODEL];       // layernorm output        32 MB
__device__ float g_xz [NROWS * 2 * DINNER];   // in-proj output         128 MB
__device__ float g_xp [NROWS * DINNER];       // conv+silu output        64 MB
__device__ float g_dt [NROWS * DINNER];       // softplus(delta)         64 MB
__device__ float g_Bm [NROWS * DSTATE];       // B projection           0.5 MB
__device__ float g_Cm [NROWS * DSTATE];       // C projection           0.5 MB
__device__ float g_y  [NROWS * DINNER];       // scan output / gated y   64 MB

// ---------------- layernorm ----------------
__global__ __launch_bounds__(256) void ln_kernel(
    const float* __restrict__ x, const float* __restrict__ w,
    const float* __restrict__ b, float* __restrict__ out)
{
    int row = blockIdx.x;
    int tid = threadIdx.x;
    const float4* xr = (const float4*)(x + (size_t)row * DMODEL);
    float4 v = xr[tid];
    float s  = v.x + v.y + v.z + v.w;
    float ss = v.x*v.x + v.y*v.y + v.z*v.z + v.w*v.w;

    // warp reduce then smem reduce (8 warps)
    #pragma unroll
    for (int o = 16; o > 0; o >>= 1) {
        s  += __shfl_xor_sync(0xffffffffu, s,  o);
        ss += __shfl_xor_sync(0xffffffffu, ss, o);
    }
    __shared__ float sh_s[8], sh_ss[8];
    int wid = tid >> 5, lid = tid & 31;
    if (lid == 0) { sh_s[wid] = s; sh_ss[wid] = ss; }
    __syncthreads();
    if (wid == 0) {
        s  = sh_s[lid & 7];
        ss = sh_ss[lid & 7];
        #pragma unroll
        for (int o = 4; o > 0; o >>= 1) {
            s  += __shfl_xor_sync(0xffffffffu, s,  o);
            ss += __shfl_xor_sync(0xffffffffu, ss, o);
        }
        if (lid == 0) { sh_s[0] = s; sh_ss[0] = ss; }
    }
    __syncthreads();
    float mean = sh_s[0] * (1.0f / DMODEL);
    float var  = sh_ss[0] * (1.0f / DMODEL) - mean * mean;
    float rstd = rsqrtf(var + 1e-5f);

    const float4 wv = ((const float4*)w)[tid];
    const float4 bv = ((const float4*)b)[tid];
    float4 o4;
    o4.x = (v.x - mean) * rstd * wv.x + bv.x;
    o4.y = (v.y - mean) * rstd * wv.y + bv.y;
    o4.z = (v.z - mean) * rstd * wv.z + bv.z;
    o4.w = (v.w - mean) * rstd * wv.w + bv.w;
    ((float4*)(out + (size_t)row * DMODEL))[tid] = o4;
}

// ---------------- generic tiled SGEMM: C = A[MxK] * B[KxN] (+ epilogue) ----------------
// epi: 0 = plain, 1 = softplus(v + bias[col]), 2 = v + resid[row*N+col]
#define BM 128
#define BN 128
#define BK 8

__global__ __launch_bounds__(256) void sgemm_kernel(
    const float* __restrict__ A, const float* __restrict__ B, float* __restrict__ C,
    int M, int N, int K,
    const float* __restrict__ bias, const float* __restrict__ resid, int epi)
{
    __shared__ float As[BK][BM];
    __shared__ float Bs[BK][BN];

    int tid = threadIdx.x;
    int bx = blockIdx.x;   // N tile
    int by = blockIdx.y;   // M tile

    int arow = tid >> 1;            // 0..127
    int acol = (tid & 1) * 4;       // 0 or 4
    int brow = tid >> 5;            // 0..7
    int bcol = (tid & 31) * 4;      // 0..124

    const float* Aptr = A + (size_t)(by * BM + arow) * K + acol;
    const float* Bptr = B + (size_t)brow * N + bx * BN + bcol;

    int tx = tid & 15, ty = tid >> 4;
    float acc[8][8];
    #pragma unroll
    for (int i = 0; i < 8; i++)
        #pragma unroll
        for (int j = 0; j < 8; j++) acc[i][j] = 0.0f;

    for (int k0 = 0; k0 < K; k0 += BK) {
        float4 av = *(const float4*)Aptr;  Aptr += BK;
        float4 bv = *(const float4*)Bptr;  Bptr += (size_t)BK * N;
        As[acol + 0][arow] = av.x;
        As[acol + 1][arow] = av.y;
        As[acol + 2][arow] = av.z;
        As[acol + 3][arow] = av.w;
        *(float4*)&Bs[brow][bcol] = bv;
        __syncthreads();

        #pragma unroll
        for (int k = 0; k < BK; k++) {
            float ra[8], rb[8];
            #pragma unroll
            for (int i = 0; i < 4; i++) {
                ((float4*)ra)[0] = *(const float4*)&As[k][ty * 8];
                ((float4*)ra)[1] = *(const float4*)&As[k][ty * 8 + 4];
                ((float4*)rb)[0] = *(const float4*)&Bs[k][tx * 8];
                ((float4*)rb)[1] = *(const float4*)&Bs[k][tx * 8 + 4];
                break;
            }
            #pragma unroll
            for (int i = 0; i < 8; i++)
                #pragma unroll
                for (int j = 0; j < 8; j++)
                    acc[i][j] = fmaf(ra[i], rb[j], acc[i][j]);
        }
        __syncthreads();
    }

    int crow0 = by * BM + ty * 8;
    int ccol0 = bx * BN + tx * 8;
    #pragma unroll
    for (int i = 0; i < 8; i++) {
        int r = crow0 + i;
        #pragma unroll
        for (int j = 0; j < 8; j += 4) {
            float4 v;
            float* pv = (float*)&v;
            #pragma unroll
            for (int jj = 0; jj < 4; jj++) {
                int c = ccol0 + j + jj;
                float val = acc[i][j + jj];
                if (epi == 1) {
                    val += bias[c];
                    // numerically-stable softplus: max(x,0)+log1p(exp(-|x|))
                    val = fmaxf(val, 0.0f) + log1pf(expf(-fabsf(val)));
                } else if (epi == 2) {
                    val += resid[(size_t)r * N + c];
                }
                pv[jj] = val;
            }
            *(float4*)(C + (size_t)r * N + ccol0 + j) = v;
        }
    }
}

// ---------------- causal depthwise conv (K=4, left pad 3) + SiLU ----------------
__global__ __launch_bounds__(256) void conv_silu_kernel(
    const float* __restrict__ xz, const float* __restrict__ cw,
    const float* __restrict__ cb, float* __restrict__ xp)
{
    int idx = blockIdx.x * 256 + threadIdx.x;    // over NROWS*DINNER
    int d  = idx & (DINNER - 1);
    int bl = idx >> 11;
    int l  = bl & (LSEQ - 1);

    float acc = cb[d];
    #pragma unroll
    for (int k = 0; k < DCONV; k++) {
        int li = l + k - (DCONV - 1);
        if (li >= 0)
            acc = fmaf(xz[(size_t)(bl + k - (DCONV - 1)) * (2 * DINNER) + d],
                       cw[d * DCONV + k], acc);
    }
    float sg = 1.0f / (1.0f + __expf(-acc));
    xp[idx] = acc * sg;
}

// ---------------- B/C projections: [8192,2048] x [2048,16] each ----------------
__global__ __launch_bounds__(256) void bc_proj_kernel(
    const float* __restrict__ xp, const float* __restrict__ Wb,
    const float* __restrict__ Wc, float* __restrict__ Bm, float* __restrict__ Cm)
{
    int row = blockIdx.x;
    int tid = threadIdx.x;
    int n  = tid & 15;          // state index
    int ks = tid >> 4;          // k-slice 0..15
    const float* xr = xp + (size_t)row * DINNER;

    float accB = 0.0f, accC = 0.0f;
    int k0 = ks * (DINNER / 16);
    #pragma unroll 4
    for (int k = k0; k < k0 + DINNER / 16; k++) {
        float xv = xr[k];
        accB = fmaf(xv, Wb[k * DSTATE + n], accB);
        accC = fmaf(xv, Wc[k * DSTATE + n], accC);
    }
    __shared__ float sB[256], sC[256];
    sB[tid] = accB; sC[tid] = accC;
    __syncthreads();
    #pragma unroll
    for (int off = 128; off >= 16; off >>= 1) {
        if (tid < off) { sB[tid] += sB[tid + off]; sC[tid] += sC[tid + off]; }
        __syncthreads();
    }
    if (tid < 16) {
        Bm[row * DSTATE + tid] = sB[tid];
        Cm[row * DSTATE + tid] = sC[tid];
    }
}

// ---------------- selective scan: 4 lanes per (b,d) channel, 4 states/lane ----------------
__global__ __launch_bounds__(64) void scan_kernel(
    const float* __restrict__ xp, const float* __restrict__ dt,
    const float* __restrict__ Bm, const float* __restrict__ Cm,
    const float* __restrict__ A_log, const float* __restrict__ Dp,
    float* __restrict__ y)
{
    int tid = threadIdx.x;
    int lc  = tid >> 2;                   // local channel 0..15
    int sub = tid & 3;                    // state group
    int c   = blockIdx.x * 16 + lc;       // global channel 0..8191
    int b   = c >> 11;
    int d   = c & (DINNER - 1);

    float4 al = *(const float4*)(A_log + d * DSTATE + sub * 4);
    float A0 = -expf(al.x), A1 = -expf(al.y), A2 = -expf(al.z), A3 = -expf(al.w);
    float Dv = Dp[d];

    float h0 = 0.f, h1 = 0.f, h2 = 0.f, h3 = 0.f;
    size_t base   = (size_t)b * LSEQ * DINNER + d;   // stride DINNER per step
    int    bcbase = b * LSEQ * DSTATE + sub * 4;     // stride DSTATE per step

    for (int t = 0; t < LSEQ; t++) {
        float xv  = xp[base];
        float dtv = dt[base];
        float4 Bv = *(const float4*)(Bm + bcbase);
        float4 Cv = *(const float4*)(Cm + bcbase);
        float dx  = dtv * xv;
        h0 = fmaf(__expf(dtv * A0), h0, dx * Bv.x);
        h1 = fmaf(__expf(dtv * A1), h1, dx * Bv.y);
        h2 = fmaf(__expf(dtv * A2), h2, dx * Bv.z);
        h3 = fmaf(__expf(dtv * A3), h3, dx * Bv.w);
        float acc = h0 * Cv.x + h1 * Cv.y + h2 * Cv.z + h3 * Cv.w;
        acc += __shfl_xor_sync(0xffffffffu, acc, 1);
        acc += __shfl_xor_sync(0xffffffffu, acc, 2);
        if (sub == 0) y[base] = fmaf(Dv, xv, acc);
        base   += DINNER;
        bcbase += DSTATE;
    }
}

// ---------------- gate: y *= silu(z) ----------------
__global__ __launch_bounds__(256) void gate_kernel(
    const float* __restrict__ xz, float* __restrict__ y)
{
    int idx = blockIdx.x * 256 + threadIdx.x;   // over NROWS*DINNER
    int d  = idx & (DINNER - 1);
    int bl = idx >> 11;
    float z = xz[(size_t)bl * (2 * DINNER) + DINNER + d];
    float sg = 1.0f / (1.0f + __expf(-z));
    y[idx] = y[idx] * z * sg;
}

// ---------------- launch ----------------
extern "C" void kernel_launch(void* const* d_in, const int* in_sizes, int n_in,
                              void* d_out, int out_size)
{
    const float* x       = (const float*)d_in[0];
    const float* norm_w  = (const float*)d_in[1];
    const float* norm_b  = (const float*)d_in[2];
    const float* W_in    = (const float*)d_in[3];
    const float* conv_w  = (const float*)d_in[4];
    const float* conv_b  = (const float*)d_in[5];
    const float* A_log   = (const float*)d_in[6];
    const float* W_b     = (const float*)d_in[7];
    const float* W_c     = (const float*)d_in[8];
    const float* W_delta = (const float*)d_in[9];
    const float* b_delta = (const float*)d_in[10];
    const float* D_param = (const float*)d_in[11];
    const float* W_out   = (const float*)d_in[12];
    float* out = (float*)d_out;

    float *xn, *xz, *xp, *dtb, *Bm, *Cm, *y;
    cudaGetSymbolAddress((void**)&xn,  g_xn);
    cudaGetSymbolAddress((void**)&xz,  g_xz);
    cudaGetSymbolAddress((void**)&xp,  g_xp);
    cudaGetSymbolAddress((void**)&dtb, g_dt);
    cudaGetSymbolAddress((void**)&Bm,  g_Bm);
    cudaGetSymbolAddress((void**)&Cm,  g_Cm);
    cudaGetSymbolAddress((void**)&y,   g_y);

    // 1) layernorm
    ln_kernel<<<NROWS, 256>>>(x, norm_w, norm_b, xn);

    // 2) xz = xn @ W_in   [8192 x 4096, K=1024]
    sgemm_kernel<<<dim3(2 * DINNER / BN, NROWS / BM), 256>>>(
        xn, W_in, xz, NROWS, 2 * DINNER, DMODEL, nullptr, nullptr, 0);

    // 3) causal conv + silu -> xp
    conv_silu_kernel<<<(NROWS * DINNER) / 256, 256>>>(xz, conv_w, conv_b, xp);

    // 4) B, C projections
    bc_proj_kernel<<<NROWS, 256>>>(xp, W_b, W_c, Bm, Cm);

    // 5) delta = softplus(xp @ W_delta + b_delta)   [8192 x 2048, K=2048]
    sgemm_kernel<<<dim3(DINNER / BN, NROWS / BM), 256>>>(
        xp, W_delta, dtb, NROWS, DINNER, DINNER, b_delta, nullptr, 1);

    // 6) selective scan -> y
    scan_kernel<<<(B_SZ * DINNER) / 16, 64>>>(xp, dtb, Bm, Cm, A_log, D_param, y);

    // 7) gate y *= silu(z)
    gate_kernel<<<(NROWS * DINNER) / 256, 256>>>(xz, y);

    // 8) out = y @ W_out + residual(x)   [8192 x 1024, K=2048]
    sgemm_kernel<<<dim3(DMODEL / BN, NROWS / BM), 256>>>(
        y, W_out, out, NROWS, DMODEL, DINNER, nullptr, x, 2);
}

// round 3
// speedup vs baseline: 1.3077x; 1.3077x over previous
#include <cuda_runtime.h>
#include <cuda_bf16.h>
#include <cstdint>

// ---------------- problem constants ----------------
#define B_SZ    4
#define LSEQ    2048
#define DMODEL  1024
#define DINNER  2048
#define DSTATE  16
#define DCONV   4
#define NROWS   (B_SZ * LSEQ)           // 8192

// ---------------- scratch (device globals; no allocation allowed) ----------------
__device__ __nv_bfloat16 g_xn_h[NROWS * DMODEL];
__device__ __nv_bfloat16 g_xn_l[NROWS * DMODEL];
__device__ float         g_xz  [(size_t)NROWS * 2 * DINNER];   // 128 MB
__device__ float         g_xp  [(size_t)NROWS * DINNER];
__device__ __nv_bfloat16 g_xp_h[NROWS * DINNER];
__device__ __nv_bfloat16 g_xp_l[NROWS * DINNER];
__device__ float         g_dtb [(size_t)NROWS * DINNER];
__device__ __nv_bfloat16 g_yg_h[NROWS * DINNER];
__device__ __nv_bfloat16 g_yg_l[NROWS * DINNER];
__device__ float         g_Bm  [NROWS * DSTATE];
__device__ float         g_Cm  [NROWS * DSTATE];
// transposed + split weights  (B operand layout [N, K], K-major)
__device__ __nv_bfloat16 g_Wi_h[2 * DINNER * DMODEL];
__device__ __nv_bfloat16 g_Wi_l[2 * DINNER * DMODEL];
__device__ __nv_bfloat16 g_Wd_h[DINNER * DINNER];
__device__ __nv_bfloat16 g_Wd_l[DINNER * DINNER];
__device__ __nv_bfloat16 g_Wo_h[DMODEL * DINNER];
__device__ __nv_bfloat16 g_Wo_l[DMODEL * DINNER];

// ---------------- helpers ----------------
__device__ __forceinline__ uint32_t smem_u32(const void* p) {
    uint32_t a;
    asm("{ .reg .u64 t; cvta.to.shared.u64 t, %1; cvt.u32.u64 %0, t; }"
        : "=r"(a) : "l"(p));
    return a;
}
__device__ __forceinline__ void split_bf16(float v, __nv_bfloat16& h, __nv_bfloat16& l) {
    h = __float2bfloat16(v);
    l = __float2bfloat16(v - __bfloat162float(h));
}
__device__ __forceinline__ uint32_t pack2bf(__nv_bfloat16 a, __nv_bfloat16 b) {
    __nv_bfloat162 t; t.x = a; t.y = b;
    return *reinterpret_cast<uint32_t*>(&t);
}
__device__ __forceinline__ void cp_async16(uint32_t dst, const void* src) {
    asm volatile("cp.async.cg.shared.global [%0], [%1], 16;"
                 :: "r"(dst), "l"(src));
}
__device__ __forceinline__ void cp_commit() {
    asm volatile("cp.async.commit_group;");
}
__device__ __forceinline__ void ldsm4(uint32_t* r, uint32_t addr) {
    asm volatile("ldmatrix.sync.aligned.m8n8.x4.shared.b16 {%0,%1,%2,%3}, [%4];"
                 : "=r"(r[0]), "=r"(r[1]), "=r"(r[2]), "=r"(r[3]) : "r"(addr));
}
__device__ __forceinline__ void mma_bf16(float* c, const uint32_t* a, uint32_t b0, uint32_t b1) {
    asm volatile(
        "mma.sync.aligned.m16n8k16.row.col.f32.bf16.bf16.f32 "
        "{%0,%1,%2,%3}, {%4,%5,%6,%7}, {%8,%9}, {%0,%1,%2,%3};"
        : "+f"(c[0]), "+f"(c[1]), "+f"(c[2]), "+f"(c[3])
        : "r"(a[0]), "r"(a[1]), "r"(a[2]), "r"(a[3]), "r"(b0), "r"(b1));
}
__device__ __forceinline__ uint32_t sw128(uint32_t off) {
    return off ^ ((off >> 3) & 0x70);
}

// ---------------- layernorm (writes bf16 hi/lo split) ----------------
__global__ __launch_bounds__(256) void ln_kernel(
    const float* __restrict__ x, const float* __restrict__ w,
    const float* __restrict__ b, __nv_bfloat16* __restrict__ oh,
    __nv_bfloat16* __restrict__ ol)
{
    int row = blockIdx.x;
    int tid = threadIdx.x;
    const float4* xr = (const float4*)(x + (size_t)row * DMODEL);
    float4 v = xr[tid];
    float s  = v.x + v.y + v.z + v.w;
    float ss = v.x*v.x + v.y*v.y + v.z*v.z + v.w*v.w;

    #pragma unroll
    for (int o = 16; o > 0; o >>= 1) {
        s  += __shfl_xor_sync(0xffffffffu, s,  o);
        ss += __shfl_xor_sync(0xffffffffu, ss, o);
    }
    __shared__ float sh_s[8], sh_ss[8];
    int wid = tid >> 5, lid = tid & 31;
    if (lid == 0) { sh_s[wid] = s; sh_ss[wid] = ss; }
    __syncthreads();
    if (wid == 0) {
        s  = sh_s[lid & 7];
        ss = sh_ss[lid & 7];
        #pragma unroll
        for (int o = 4; o > 0; o >>= 1) {
            s  += __shfl_xor_sync(0xffffffffu, s,  o);
            ss += __shfl_xor_sync(0xffffffffu, ss, o);
        }
        if (lid == 0) { sh_s[0] = s; sh_ss[0] = ss; }
    }
    __syncthreads();
    float mean = sh_s[0] * (1.0f / DMODEL);
    float var  = sh_ss[0] * (1.0f / DMODEL) - mean * mean;
    float rstd = rsqrtf(var + 1e-5f);

    const float4 wv = ((const float4*)w)[tid];
    const float4 bv = ((const float4*)b)[tid];
    float o0 = (v.x - mean) * rstd * wv.x + bv.x;
    float o1 = (v.y - mean) * rstd * wv.y + bv.y;
    float o2 = (v.z - mean) * rstd * wv.z + bv.z;
    float o3 = (v.w - mean) * rstd * wv.w + bv.w;
    __nv_bfloat16 h0,h1,h2,h3,l0,l1,l2,l3;
    split_bf16(o0,h0,l0); split_bf16(o1,h1,l1);
    split_bf16(o2,h2,l2); split_bf16(o3,h3,l3);
    uint2 uh = make_uint2(pack2bf(h0,h1), pack2bf(h2,h3));
    uint2 ul = make_uint2(pack2bf(l0,l1), pack2bf(l2,l3));
    ((uint2*)(oh + (size_t)row * DMODEL))[tid] = uh;
    ((uint2*)(ol + (size_t)row * DMODEL))[tid] = ul;
}

// ---------------- weight transpose + bf16 split: W[K,N] -> T[N,K] hi/lo ----------------
__global__ __launch_bounds__(256) void tsplit_kernel(
    const float* __restrict__ W, __nv_bfloat16* __restrict__ Th,
    __nv_bfloat16* __restrict__ Tl, int K, int N)
{
    __shared__ float tile[32][33];
    int bx = blockIdx.x * 32;   // n
    int by = blockIdx.y * 32;   // k
    int tx = threadIdx.x & 31, ty = threadIdx.x >> 5;
    #pragma unroll
    for (int i = 0; i < 4; i++)
        tile[ty + 8*i][tx] = W[(size_t)(by + ty + 8*i) * N + bx + tx];
    __syncthreads();
    #pragma unroll
    for (int i = 0; i < 4; i++) {
        float v = tile[tx][ty + 8*i];
        int n = bx + ty + 8*i, k = by + tx;
        __nv_bfloat16 h, l; split_bf16(v, h, l);
        Th[(size_t)n * K + k] = h;
        Tl[(size_t)n * K + k] = l;
    }
}

// ---------------- mma.sync bf16x3 GEMM: C[M,N] = A[M,K] * Bt[N,K]^T ----------------
// 128x128 CTA tile, BK=64, 3-stage cp.async pipeline, SW128 smem.
// epi: 0 plain, 1 softplus(v + bias[col]), 2 v + resid[row*N+col]
#define STAGES       3
#define STAGE_BYTES  65536
#define OFF_AH       0
#define OFF_AL       16384
#define OFF_BH       32768
#define OFF_BL       49152
#define G_SMEM_BYTES (STAGES * STAGE_BYTES)

__global__ __launch_bounds__(256, 1) void gemm_mma_kernel(
    const __nv_bfloat16* __restrict__ Ah, const __nv_bfloat16* __restrict__ Al,
    const __nv_bfloat16* __restrict__ Bh, const __nv_bfloat16* __restrict__ Bl,
    float* __restrict__ C, int M, int N, int K,
    const float* __restrict__ bias, const float* __restrict__ resid, int epi)
{
    extern __shared__ __align__(1024) char smem[];
    const int tid  = threadIdx.x;
    const int lane = tid & 31;
    const int wid  = tid >> 5;
    const int wm   = wid >> 2;      // 0..1  (m)
    const int wn   = wid & 3;       // 0..3  (n)
    const int m0   = blockIdx.y * 128;
    const int n0   = blockIdx.x * 128;
    const uint32_t sbase = smem_u32(smem);

    // ---- stage fill via cp.async ----
    auto fill = [&](int slot, int kc) {
        uint32_t sb = sbase + slot * STAGE_BYTES;
        int k0 = kc * 64;
        #pragma unroll
        for (int i = 0; i < 4; i++) {
            int idx = tid + i * 256;          // 0..1023
            int r = idx >> 3, c8 = idx & 7;
            uint32_t sw = sw128((uint32_t)(r * 128 + c8 * 16));
            size_t ga = (size_t)(m0 + r) * K + k0 + c8 * 8;
            size_t gb = (size_t)(n0 + r) * K + k0 + c8 * 8;
            cp_async16(sb + OFF_AH + sw, Ah + ga);
            cp_async16(sb + OFF_AL + sw, Al + ga);
            cp_async16(sb + OFF_BH + sw, Bh + gb);
            cp_async16(sb + OFF_BL + sw, Bl + gb);
        }
    };

    float acc[4][4][4];
    #pragma unroll
    for (int i = 0; i < 4; i++)
        #pragma unroll
        for (int j = 0; j < 4; j++)
            #pragma unroll
            for (int q = 0; q < 4; q++) acc[i][j][q] = 0.0f;

    const int nch = K >> 6;

    // prologue: stages 0..STAGES-2
    fill(0, 0); cp_commit();
    fill(1, 1); cp_commit();

    const int rowA = wm * 64 + (lane & 15);
    const int rowB = wn * 32 + (lane & 15);
    const int colb_base = (lane >> 4) << 4;   // 0 or 16

    for (int c = 0; c < nch; c++) {
        asm volatile("cp.async.wait_group 1;" ::: "memory");
        __syncthreads();

        if (c + STAGES - 1 < nch) fill((c + STAGES - 1) % STAGES, c + STAGES - 1);
        cp_commit();

        uint32_t sa = sbase + (c % STAGES) * STAGE_BYTES;
        #pragma unroll
        for (int ks = 0; ks < 4; ks++) {
            int colb = ks * 32 + colb_base;
            uint32_t ahi[4][4], alo[4][4], bhi[2][4], blo[2][4];
            #pragma unroll
            for (int mt = 0; mt < 4; mt++) {
                uint32_t sw = sw128((uint32_t)((rowA + mt * 16) * 128 + colb));
                ldsm4(ahi[mt], sa + OFF_AH + sw);
                ldsm4(alo[mt], sa + OFF_AL + sw);
            }
            #pragma unroll
            for (int np = 0; np < 2; np++) {
                uint32_t sw = sw128((uint32_t)((rowB + np * 16) * 128 + colb));
                ldsm4(bhi[np], sa + OFF_BH + sw);
                ldsm4(blo[np], sa + OFF_BL + sw);
            }
            #pragma unroll
            for (int mt = 0; mt < 4; mt++) {
                #pragma unroll
                for (int n8 = 0; n8 < 4; n8++) {
                    int np = n8 >> 1, sel = n8 & 1;
                    mma_bf16(acc[mt][n8], ahi[mt], bhi[np][sel], bhi[np][sel + 2]);
                    mma_bf16(acc[mt][n8], ahi[mt], blo[np][sel], blo[np][sel + 2]);
                    mma_bf16(acc[mt][n8], alo[mt], bhi[np][sel], bhi[np][sel + 2]);
                }
            }
        }
        __syncthreads();
    }

    // ---- epilogue ----
    int gr  = lane >> 2;
    int gc2 = (lane & 3) * 2;
    #pragma unroll
    for (int mt = 0; mt < 4; mt++) {
        #pragma unroll
        for (int h2 = 0; h2 < 2; h2++) {
            size_t row = (size_t)(m0 + wm * 64 + mt * 16 + gr + h2 * 8);
            #pragma unroll
            for (int n8 = 0; n8 < 4; n8++) {
                int col = n0 + wn * 32 + n8 * 8 + gc2;
                float v0 = acc[mt][n8][h2 * 2 + 0];
                float v1 = acc[mt][n8][h2 * 2 + 1];
                if (epi == 1) {
                    v0 += bias[col];
                    v1 += bias[col + 1];
                    v0 = fmaxf(v0, 0.f) + log1pf(expf(-fabsf(v0)));
                    v1 = fmaxf(v1, 0.f) + log1pf(expf(-fabsf(v1)));
                } else if (epi == 2) {
                    v0 += resid[row * N + col];
                    v1 += resid[row * N + col + 1];
                }
                *(float2*)(C + row * N + col) = make_float2(v0, v1);
            }
        }
    }
}

// ---------------- causal depthwise conv (K=4) + SiLU; writes fp32 + bf16 split ----------------
__global__ __launch_bounds__(256) void conv_silu_kernel(
    const float* __restrict__ xz, const float* __restrict__ cw,
    const float* __restrict__ cb, float* __restrict__ xp,
    __nv_bfloat16* __restrict__ xph, __nv_bfloat16* __restrict__ xpl)
{
    int idx = blockIdx.x * 256 + threadIdx.x;
    int d  = idx & (DINNER - 1);
    int bl = idx >> 11;
    int l  = bl & (LSEQ - 1);

    float acc = cb[d];
    #pragma unroll
    for (int k = 0; k < DCONV; k++) {
        int li = l + k - (DCONV - 1);
        if (li >= 0)
            acc = fmaf(xz[(size_t)(bl + k - (DCONV - 1)) * (2 * DINNER) + d],
                       cw[d * DCONV + k], acc);
    }
    float sg = 1.0f / (1.0f + __expf(-acc));
    float v = acc * sg;
    xp[idx] = v;
    __nv_bfloat16 h, lo; split_bf16(v, h, lo);
    xph[idx] = h; xpl[idx] = lo;
}

// ---------------- B/C projections: 16 rows per block ----------------
__global__ __launch_bounds__(256) void bc_proj_kernel(
    const float* __restrict__ xp, const float* __restrict__ Wb,
    const float* __restrict__ Wc, float* __restrict__ Bm, float* __restrict__ Cm)
{
    __shared__ float sredB[8][16][16];
    __shared__ float sredC[8][16][16];
    int row0 = blockIdx.x * 16;
    int tid = threadIdx.x;
    int n = tid & 15, ks = tid >> 4;
    int lane = tid & 31, w = tid >> 5;
    float aB[16], aC[16];
    #pragma unroll
    for (int r = 0; r < 16; r++) { aB[r] = 0.f; aC[r] = 0.f; }

    const float* xb = xp + (size_t)row0 * DINNER;
    int k0 = ks * 128;
    for (int k = k0; k < k0 + 128; k += 4) {
        float wb0 = Wb[(k+0)*DSTATE+n], wb1 = Wb[(k+1)*DSTATE+n];
        float wb2 = Wb[(k+2)*DSTATE+n], wb3 = Wb[(k+3)*DSTATE+n];
        float wc0 = Wc[(k+0)*DSTATE+n], wc1 = Wc[(k+1)*DSTATE+n];
        float wc2 = Wc[(k+2)*DSTATE+n], wc3 = Wc[(k+3)*DSTATE+n];
        #pragma unroll
        for (int r = 0; r < 16; r++) {
            float4 xq = *(const float4*)(xb + r * DINNER + k);
            aB[r] = fmaf(xq.x, wb0, fmaf(xq.y, wb1, fmaf(xq.z, wb2, fmaf(xq.w, wb3, aB[r]))));
            aC[r] = fmaf(xq.x, wc0, fmaf(xq.y, wc1, fmaf(xq.z, wc2, fmaf(xq.w, wc3, aC[r]))));
        }
    }
    #pragma unroll
    for (int r = 0; r < 16; r++) {
        float vB = aB[r] + __shfl_xor_sync(0xffffffffu, aB[r], 16);
        float vC = aC[r] + __shfl_xor_sync(0xffffffffu, aC[r], 16);
        if (lane < 16) { sredB[w][r][lane] = vB; sredC[w][r][lane] = vC; }
    }
    __syncthreads();
    int rr = tid >> 4, nn = tid & 15;
    float sB = 0.f, sC = 0.f;
    #pragma unroll
    for (int w2 = 0; w2 < 8; w2++) { sB += sredB[w2][rr][nn]; sC += sredC[w2][rr][nn]; }
    Bm[(row0 + rr) * DSTATE + nn] = sB;
    Cm[(row0 + rr) * DSTATE + nn] = sC;
}

// ---------------- selective scan + fused gate, writes bf16 split ----------------
__global__ __launch_bounds__(64) void scan_kernel(
    const float* __restrict__ xp, const float* __restrict__ dt,
    const float* __restrict__ Bm, const float* __restrict__ Cm,
    const float* __restrict__ A_log, const float* __restrict__ Dp,
    const float* __restrict__ xz,
    __nv_bfloat16* __restrict__ ygh, __nv_bfloat16* __restrict__ ygl)
{
    int tid = threadIdx.x;
    int lc  = tid >> 2;
    int sub = tid & 3;
    int c   = blockIdx.x * 16 + lc;
    int b   = c >> 11;
    int d   = c & (DINNER - 1);

    float4 al = *(const float4*)(A_log + d * DSTATE + sub * 4);
    float A0 = -expf(al.x), A1 = -expf(al.y), A2 = -expf(al.z), A3 = -expf(al.w);
    float Dv = Dp[d];

    float h0 = 0.f, h1 = 0.f, h2 = 0.f, h3 = 0.f;
    size_t base   = (size_t)b * LSEQ * DINNER + d;
    size_t zidx   = (size_t)b * LSEQ * (2 * DINNER) + DINNER + d;
    int    bcbase = b * LSEQ * DSTATE + sub * 4;

    for (int t = 0; t < LSEQ; t++) {
        float xv  = xp[base];
        float dtv = dt[base];
        float4 Bv = *(const float4*)(Bm + bcbase);
        float4 Cv = *(const float4*)(Cm + bcbase);
        float dx  = dtv * xv;
        h0 = fmaf(__expf(dtv * A0), h0, dx * Bv.x);
        h1 = fmaf(__expf(dtv * A1), h1, dx * Bv.y);
        h2 = fmaf(__expf(dtv * A2), h2, dx * Bv.z);
        h3 = fmaf(__expf(dtv * A3), h3, dx * Bv.w);
        float acc = h0 * Cv.x + h1 * Cv.y + h2 * Cv.z + h3 * Cv.w;
        acc += __shfl_xor_sync(0xffffffffu, acc, 1);
        acc += __shfl_xor_sync(0xffffffffu, acc, 2);
        if (sub == 0) {
            float yv = fmaf(Dv, xv, acc);
            float z  = xz[zidx];
            float sg = 1.0f / (1.0f + __expf(-z));
            yv *= z * sg;
            __nv_bfloat16 hh, ll; split_bf16(yv, hh, ll);
            ygh[base] = hh; ygl[base] = ll;
        }
        base   += DINNER;
        zidx   += 2 * DINNER;
        bcbase += DSTATE;
    }
}

// ---------------- launch ----------------
extern "C" void kernel_launch(void* const* d_in, const int* in_sizes, int n_in,
                              void* d_out, int out_size)
{
    const float* x       = (const float*)d_in[0];
    const float* norm_w  = (const float*)d_in[1];
    const float* norm_b  = (const float*)d_in[2];
    const float* W_in    = (const float*)d_in[3];
    const float* conv_w  = (const float*)d_in[4];
    const float* conv_b  = (const float*)d_in[5];
    const float* A_log   = (const float*)d_in[6];
    const float* W_b     = (const float*)d_in[7];
    const float* W_c     = (const float*)d_in[8];
    const float* W_delta = (const float*)d_in[9];
    const float* b_delta = (const float*)d_in[10];
    const float* D_param = (const float*)d_in[11];
    const float* W_out   = (const float*)d_in[12];
    float* out = (float*)d_out;

    __nv_bfloat16 *xnh, *xnl, *xph, *xpl, *ygh, *ygl;
    __nv_bfloat16 *Wih, *Wil, *Wdh, *Wdl, *Woh, *Wol;
    float *xz, *xp, *dtb, *Bm, *Cm;
    cudaGetSymbolAddress((void**)&xnh, g_xn_h);
    cudaGetSymbolAddress((void**)&xnl, g_xn_l);
    cudaGetSymbolAddress((void**)&xz,  g_xz);
    cudaGetSymbolAddress((void**)&xp,  g_xp);
    cudaGetSymbolAddress((void**)&xph, g_xp_h);
    cudaGetSymbolAddress((void**)&xpl, g_xp_l);
    cudaGetSymbolAddress((void**)&dtb, g_dtb);
    cudaGetSymbolAddress((void**)&ygh, g_yg_h);
    cudaGetSymbolAddress((void**)&ygl, g_yg_l);
    cudaGetSymbolAddress((void**)&Bm,  g_Bm);
    cudaGetSymbolAddress((void**)&Cm,  g_Cm);
    cudaGetSymbolAddress((void**)&Wih, g_Wi_h);
    cudaGetSymbolAddress((void**)&Wil, g_Wi_l);
    cudaGetSymbolAddress((void**)&Wdh, g_Wd_h);
    cudaGetSymbolAddress((void**)&Wdl, g_Wd_l);
    cudaGetSymbolAddress((void**)&Woh, g_Wo_h);
    cudaGetSymbolAddress((void**)&Wol, g_Wo_l);

    cudaFuncSetAttribute(gemm_mma_kernel,
                         cudaFuncAttributeMaxDynamicSharedMemorySize, G_SMEM_BYTES);

    // weight transpose + split (runs every call; weights are inputs)
    tsplit_kernel<<<dim3(2 * DINNER / 32, DMODEL / 32), 256>>>(W_in, Wih, Wil, DMODEL, 2 * DINNER);
    tsplit_kernel<<<dim3(DINNER / 32, DINNER / 32), 256>>>(W_delta, Wdh, Wdl, DINNER, DINNER);
    tsplit_kernel<<<dim3(DMODEL / 32, DINNER / 32), 256>>>(W_out, Woh, Wol, DINNER, DMODEL);

    // 1) layernorm -> xn hi/lo
    ln_kernel<<<NROWS, 256>>>(x, norm_w, norm_b, xnh, xnl);

    // 2) xz = xn @ W_in   [8192 x 4096, K=1024]
    gemm_mma_kernel<<<dim3(2 * DINNER / 128, NROWS / 128), 256, G_SMEM_BYTES>>>(
        xnh, xnl, Wih, Wil, xz, NROWS, 2 * DINNER, DMODEL, nullptr, nullptr, 0);

    // 3) conv + silu -> xp (+ hi/lo)
    conv_silu_kernel<<<(NROWS * DINNER) / 256, 256>>>(xz, conv_w, conv_b, xp, xph, xpl);

    // 4) B, C projections
    bc_proj_kernel<<<NROWS / 16, 256>>>(xp, W_b, W_c, Bm, Cm);

    // 5) delta = softplus(xp @ W_delta + b_delta)   [8192 x 2048, K=2048]
    gemm_mma_kernel<<<dim3(DINNER / 128, NROWS / 128), 256, G_SMEM_BYTES>>>(
        xph, xpl, Wdh, Wdl, dtb, NROWS, DINNER, DINNER, b_delta, nullptr, 1);

    // 6) selective scan + fused gate -> yg hi/lo
    scan_kernel<<<(B_SZ * DINNER) / 16, 64>>>(xp, dtb, Bm, Cm, A_log, D_param, xz, ygh, ygl);

    // 7) out = yg @ W_out + residual(x)   [8192 x 1024, K=2048]
    gemm_mma_kernel<<<dim3(DMODEL / 128, NROWS / 128), 256, G_SMEM_BYTES>>>(
        ygh, ygl, Woh, Wol, out, NROWS, DMODEL, DINNER, nullptr, x, 2);
}

// round 4
// speedup vs baseline: 3.4000x; 2.5999x over previous
#include <cuda_runtime.h>
#include <cuda_bf16.h>
#include <cuda_fp16.h>
#include <cstdint>

// ---------------- problem constants ----------------
#define B_SZ    4
#define LSEQ    2048
#define DMODEL  1024
#define DINNER  2048
#define DSTATE  16
#define DCONV   4
#define NROWS   (B_SZ * LSEQ)           // 8192

// ---------------- scratch (device globals; no allocation allowed) ----------------
__device__ __half g_xn_h[NROWS * DMODEL];
__device__ float  g_xz  [(size_t)NROWS * 2 * DINNER];   // 128 MB
__device__ float  g_xp  [(size_t)NROWS * DINNER];
__device__ __half g_xp_h[NROWS * DINNER];
__device__ float  g_dtb [(size_t)NROWS * DINNER];
__device__ __half g_yg_h[NROWS * DINNER];
__device__ float  g_Bm  [NROWS * DSTATE];
__device__ float  g_Cm  [NROWS * DSTATE];
// transposed fp16 weights (B operand layout [N, K], K-major)
__device__ __half g_Wi_h[2 * DINNER * DMODEL];
__device__ __half g_Wd_h[DINNER * DINNER];
__device__ __half g_Wo_h[DMODEL * DINNER];

// ---------------- helpers ----------------
__device__ __forceinline__ uint32_t smem_u32(const void* p) {
    uint32_t a;
    asm("{ .reg .u64 t; cvta.to.shared.u64 t, %1; cvt.u32.u64 %0, t; }"
        : "=r"(a) : "l"(p));
    return a;
}
__device__ __forceinline__ void cp_async16(uint32_t dst, const void* src) {
    asm volatile("cp.async.cg.shared.global [%0], [%1], 16;"
                 :: "r"(dst), "l"(src));
}
__device__ __forceinline__ void cp_commit() {
    asm volatile("cp.async.commit_group;");
}
__device__ __forceinline__ void ldsm4(uint32_t* r, uint32_t addr) {
    asm volatile("ldmatrix.sync.aligned.m8n8.x4.shared.b16 {%0,%1,%2,%3}, [%4];"
                 : "=r"(r[0]), "=r"(r[1]), "=r"(r[2]), "=r"(r[3]) : "r"(addr));
}
__device__ __forceinline__ void mma_fp16(float* c, const uint32_t* a, uint32_t b0, uint32_t b1) {
    asm volatile(
        "mma.sync.aligned.m16n8k16.row.col.f32.f16.f16.f32 "
        "{%0,%1,%2,%3}, {%4,%5,%6,%7}, {%8,%9}, {%0,%1,%2,%3};"
        : "+f"(c[0]), "+f"(c[1]), "+f"(c[2]), "+f"(c[3])
        : "r"(a[0]), "r"(a[1]), "r"(a[2]), "r"(a[3]), "r"(b0), "r"(b1));
}
__device__ __forceinline__ uint32_t sw128(uint32_t off) {
    return off ^ ((off >> 3) & 0x70);
}
__device__ __forceinline__ uint32_t pack2h(float a, float b) {
    __half2 t = __floats2half2_rn(a, b);
    return *reinterpret_cast<uint32_t*>(&t);
}

// ---------------- layernorm (writes fp16) ----------------
__global__ __launch_bounds__(256) void ln_kernel(
    const float* __restrict__ x, const float* __restrict__ w,
    const float* __restrict__ b, __half* __restrict__ oh)
{
    int row = blockIdx.x;
    int tid = threadIdx.x;
    const float4* xr = (const float4*)(x + (size_t)row * DMODEL);
    float4 v = xr[tid];
    float s  = v.x + v.y + v.z + v.w;
    float ss = v.x*v.x + v.y*v.y + v.z*v.z + v.w*v.w;

    #pragma unroll
    for (int o = 16; o > 0; o >>= 1) {
        s  += __shfl_xor_sync(0xffffffffu, s,  o);
        ss += __shfl_xor_sync(0xffffffffu, ss, o);
    }
    __shared__ float sh_s[8], sh_ss[8];
    int wid = tid >> 5, lid = tid & 31;
    if (lid == 0) { sh_s[wid] = s; sh_ss[wid] = ss; }
    __syncthreads();
    if (wid == 0) {
        s  = sh_s[lid & 7];
        ss = sh_ss[lid & 7];
        #pragma unroll
        for (int o = 4; o > 0; o >>= 1) {
            s  += __shfl_xor_sync(0xffffffffu, s,  o);
            ss += __shfl_xor_sync(0xffffffffu, ss, o);
        }
        if (lid == 0) { sh_s[0] = s; sh_ss[0] = ss; }
    }
    __syncthreads();
    float mean = sh_s[0] * (1.0f / DMODEL);
    float var  = sh_ss[0] * (1.0f / DMODEL) - mean * mean;
    float rstd = rsqrtf(var + 1e-5f);

    const float4 wv = ((const float4*)w)[tid];
    const float4 bv = ((const float4*)b)[tid];
    float o0 = (v.x - mean) * rstd * wv.x + bv.x;
    float o1 = (v.y - mean) * rstd * wv.y + bv.y;
    float o2 = (v.z - mean) * rstd * wv.z + bv.z;
    float o3 = (v.w - mean) * rstd * wv.w + bv.w;
    uint2 uh = make_uint2(pack2h(o0, o1), pack2h(o2, o3));
    ((uint2*)(oh + (size_t)row * DMODEL))[tid] = uh;
}

// ---------------- weight transpose + fp16 convert: W[K,N] -> T[N,K] ----------------
__global__ __launch_bounds__(256) void wsplit_kernel(
    const float* __restrict__ W, __half* __restrict__ Th, int K, int N)
{
    __shared__ float tile[32][33];
    int bx = blockIdx.x * 32;   // n
    int by = blockIdx.y * 32;   // k
    int tx = threadIdx.x & 31, ty = threadIdx.x >> 5;
    #pragma unroll
    for (int i = 0; i < 4; i++)
        tile[ty + 8*i][tx] = W[(size_t)(by + ty + 8*i) * N + bx + tx];
    __syncthreads();
    #pragma unroll
    for (int i = 0; i < 4; i++) {
        float v = tile[tx][ty + 8*i];
        int n = bx + ty + 8*i, k = by + tx;
        Th[(size_t)n * K + k] = __float2half_rn(v);
    }
}

// ---------------- mma.sync fp16 GEMM: C[M,N] = A[M,K] * Bt[N,K]^T ----------------
// 128x128 CTA tile, BK=64, 3-stage cp.async pipeline, SW128 smem, 2 CTAs/SM.
// epi: 0 plain, 1 softplus(v + bias[col]), 2 v + resid[row*N+col]
#define STAGES       3
#define STAGE_BYTES  32768
#define OFF_A        0
#define OFF_B        16384
#define G_SMEM_BYTES (STAGES * STAGE_BYTES)

__global__ __launch_bounds__(256, 2) void gemm_mma_kernel(
    const __half* __restrict__ Ah, const __half* __restrict__ Bh,
    float* __restrict__ C, int M, int N, int K,
    const float* __restrict__ bias, const float* __restrict__ resid, int epi)
{
    extern __shared__ __align__(1024) char smem[];
    const int tid  = threadIdx.x;
    const int lane = tid & 31;
    const int wid  = tid >> 5;
    const int wm   = wid >> 2;      // 0..1  (m)
    const int wn   = wid & 3;       // 0..3  (n)
    const int m0   = blockIdx.y * 128;
    const int n0   = blockIdx.x * 128;
    const uint32_t sbase = smem_u32(smem);

    // ---- stage fill via cp.async: A[128x64] + B[128x64] fp16, SW128 ----
    auto fill = [&](int slot, int kc) {
        uint32_t sb = sbase + slot * STAGE_BYTES;
        int k0 = kc * 64;
        #pragma unroll
        for (int i = 0; i < 4; i++) {
            int idx = tid + i * 256;          // 0..1023
            int r = idx >> 3, c8 = idx & 7;
            uint32_t sw = sw128((uint32_t)(r * 128 + c8 * 16));
            size_t ga = (size_t)(m0 + r) * K + k0 + c8 * 8;
            size_t gb = (size_t)(n0 + r) * K + k0 + c8 * 8;
            cp_async16(sb + OFF_A + sw, Ah + ga);
            cp_async16(sb + OFF_B + sw, Bh + gb);
        }
    };

    float acc[4][4][4];
    #pragma unroll
    for (int i = 0; i < 4; i++)
        #pragma unroll
        for (int j = 0; j < 4; j++)
            #pragma unroll
            for (int q = 0; q < 4; q++) acc[i][j][q] = 0.0f;

    const int nch = K >> 6;

    fill(0, 0); cp_commit();
    fill(1, 1); cp_commit();

    const int rowA = wm * 64 + (lane & 15);
    const int rowB = wn * 32 + (lane & 15);
    const int colb_base = (lane >> 4) << 4;   // 0 or 16

    for (int c = 0; c < nch; c++) {
        asm volatile("cp.async.wait_group 1;" ::: "memory");
        __syncthreads();

        if (c + STAGES - 1 < nch) fill((c + STAGES - 1) % STAGES, c + STAGES - 1);
        cp_commit();

        uint32_t sa = sbase + (c % STAGES) * STAGE_BYTES;
        #pragma unroll
        for (int ks = 0; ks < 4; ks++) {
            int colb = ks * 32 + colb_base;
            uint32_t a[4][4], b[2][4];
            #pragma unroll
            for (int mt = 0; mt < 4; mt++) {
                uint32_t sw = sw128((uint32_t)((rowA + mt * 16) * 128 + colb));
                ldsm4(a[mt], sa + OFF_A + sw);
            }
            #pragma unroll
            for (int np = 0; np < 2; np++) {
                uint32_t sw = sw128((uint32_t)((rowB + np * 16) * 128 + colb));
                ldsm4(b[np], sa + OFF_B + sw);
            }
            #pragma unroll
            for (int mt = 0; mt < 4; mt++) {
                #pragma unroll
                for (int n8 = 0; n8 < 4; n8++) {
                    int np = n8 >> 1, sel = n8 & 1;
                    mma_fp16(acc[mt][n8], a[mt], b[np][sel], b[np][sel + 2]);
                }
            }
        }
        __syncthreads();
    }

    // ---- epilogue ----
    int gr  = lane >> 2;
    int gc2 = (lane & 3) * 2;
    #pragma unroll
    for (int mt = 0; mt < 4; mt++) {
        #pragma unroll
        for (int h2 = 0; h2 < 2; h2++) {
            size_t row = (size_t)(m0 + wm * 64 + mt * 16 + gr + h2 * 8);
            #pragma unroll
            for (int n8 = 0; n8 < 4; n8++) {
                int col = n0 + wn * 32 + n8 * 8 + gc2;
                float v0 = acc[mt][n8][h2 * 2 + 0];
                float v1 = acc[mt][n8][h2 * 2 + 1];
                if (epi == 1) {
                    v0 += bias[col];
                    v1 += bias[col + 1];
                    v0 = fmaxf(v0, 0.f) + log1pf(expf(-fabsf(v0)));
                    v1 = fmaxf(v1, 0.f) + log1pf(expf(-fabsf(v1)));
                } else if (epi == 2) {
                    v0 += resid[row * N + col];
                    v1 += resid[row * N + col + 1];
                }
                *(float2*)(C + row * N + col) = make_float2(v0, v1);
            }
        }
    }
}

// ---------------- causal depthwise conv (K=4) + SiLU; writes fp32 + fp16 ----------------
__global__ __launch_bounds__(256) void conv_silu_kernel(
    const float* __restrict__ xz, const float* __restrict__ cw,
    const float* __restrict__ cb, float* __restrict__ xp,
    __half* __restrict__ xph)
{
    int idx = blockIdx.x * 256 + threadIdx.x;
    int d  = idx & (DINNER - 1);
    int bl = idx >> 11;
    int l  = bl & (LSEQ - 1);

    float acc = cb[d];
    #pragma unroll
    for (int k = 0; k < DCONV; k++) {
        int li = l + k - (DCONV - 1);
        if (li >= 0)
            acc = fmaf(xz[(size_t)(bl + k - (DCONV - 1)) * (2 * DINNER) + d],
                       cw[d * DCONV + k], acc);
    }
    float sg = 1.0f / (1.0f + __expf(-acc));
    float v = acc * sg;
    xp[idx] = v;
    xph[idx] = __float2half_rn(v);
}

// ---------------- B/C projections: 16 rows per block ----------------
__global__ __launch_bounds__(256) void bc_proj_kernel(
    const float* __restrict__ xp, const float* __restrict__ Wb,
    const float* __restrict__ Wc, float* __restrict__ Bm, float* __restrict__ Cm)
{
    __shared__ float sredB[8][16][16];
    __shared__ float sredC[8][16][16];
    int row0 = blockIdx.x * 16;
    int tid = threadIdx.x;
    int n = tid & 15, ks = tid >> 4;
    int lane = tid & 31, w = tid >> 5;
    float aB[16], aC[16];
    #pragma unroll
    for (int r = 0; r < 16; r++) { aB[r] = 0.f; aC[r] = 0.f; }

    const float* xb = xp + (size_t)row0 * DINNER;
    int k0 = ks * 128;
    for (int k = k0; k < k0 + 128; k += 4) {
        float wb0 = Wb[(k+0)*DSTATE+n], wb1 = Wb[(k+1)*DSTATE+n];
        float wb2 = Wb[(k+2)*DSTATE+n], wb3 = Wb[(k+3)*DSTATE+n];
        float wc0 = Wc[(k+0)*DSTATE+n], wc1 = Wc[(k+1)*DSTATE+n];
        float wc2 = Wc[(k+2)*DSTATE+n], wc3 = Wc[(k+3)*DSTATE+n];
        #pragma unroll
        for (int r = 0; r < 16; r++) {
            float4 xq = *(const float4*)(xb + r * DINNER + k);
            aB[r] = fmaf(xq.x, wb0, fmaf(xq.y, wb1, fmaf(xq.z, wb2, fmaf(xq.w, wb3, aB[r]))));
            aC[r] = fmaf(xq.x, wc0, fmaf(xq.y, wc1, fmaf(xq.z, wc2, fmaf(xq.w, wc3, aC[r]))));
        }
    }
    #pragma unroll
    for (int r = 0; r < 16; r++) {
        float vB = aB[r] + __shfl_xor_sync(0xffffffffu, aB[r], 16);
        float vC = aC[r] + __shfl_xor_sync(0xffffffffu, aC[r], 16);
        if (lane < 16) { sredB[w][r][lane] = vB; sredC[w][r][lane] = vC; }
    }
    __syncthreads();
    int rr = tid >> 4, nn = tid & 15;
    float sB = 0.f, sC = 0.f;
    #pragma unroll
    for (int w2 = 0; w2 < 8; w2++) { sB += sredB[w2][rr][nn]; sC += sredC[w2][rr][nn]; }
    Bm[(row0 + rr) * DSTATE + nn] = sB;
    Cm[(row0 + rr) * DSTATE + nn] = sC;
}

// ---------------- selective scan + fused gate, unroll-4 prefetch ----------------
__global__ __launch_bounds__(64) void scan_kernel(
    const float* __restrict__ xp, const float* __restrict__ dt,
    const float* __restrict__ Bm, const float* __restrict__ Cm,
    const float* __restrict__ A_log, const float* __restrict__ Dp,
    const float* __restrict__ xz, __half* __restrict__ ygh)
{
    int tid = threadIdx.x;
    int lc  = tid >> 2;
    int sub = tid & 3;
    int c   = blockIdx.x * 16 + lc;
    int b   = c >> 11;
    int d   = c & (DINNER - 1);

    float4 al = *(const float4*)(A_log + d * DSTATE + sub * 4);
    float A0 = -expf(al.x), A1 = -expf(al.y), A2 = -expf(al.z), A3 = -expf(al.w);
    float Dv = Dp[d];

    float h0 = 0.f, h1 = 0.f, h2 = 0.f, h3 = 0.f;
    size_t base   = (size_t)b * LSEQ * DINNER + d;
    size_t zidx   = (size_t)b * LSEQ * (2 * DINNER) + DINNER + d;
    int    bcbase = b * LSEQ * DSTATE + sub * 4;

    for (int t0 = 0; t0 < LSEQ; t0 += 4) {
        // batch independent loads for 4 steps (MLP ~18)
        float  xv[4], dv[4], zv[4];
        float4 Bv[4], Cv[4];
        #pragma unroll
        for (int u = 0; u < 4; u++) {
            xv[u] = xp[base + (size_t)u * DINNER];
            dv[u] = dt[base + (size_t)u * DINNER];
            Bv[u] = *(const float4*)(Bm + bcbase + u * DSTATE);
            Cv[u] = *(const float4*)(Cm + bcbase + u * DSTATE);
        }
        if (sub == 0) {
            #pragma unroll
            for (int u = 0; u < 4; u++)
                zv[u] = xz[zidx + (size_t)u * 2 * DINNER];
        }
        #pragma unroll
        for (int u = 0; u < 4; u++) {
            float dx = dv[u] * xv[u];
            h0 = fmaf(__expf(dv[u] * A0), h0, dx * Bv[u].x);
            h1 = fmaf(__expf(dv[u] * A1), h1, dx * Bv[u].y);
            h2 = fmaf(__expf(dv[u] * A2), h2, dx * Bv[u].z);
            h3 = fmaf(__expf(dv[u] * A3), h3, dx * Bv[u].w);
            float acc = h0 * Cv[u].x + h1 * Cv[u].y + h2 * Cv[u].z + h3 * Cv[u].w;
            acc += __shfl_xor_sync(0xffffffffu, acc, 1);
            acc += __shfl_xor_sync(0xffffffffu, acc, 2);
            if (sub == 0) {
                float yv = fmaf(Dv, xv[u], acc);
                float z  = zv[u];
                float sg = 1.0f / (1.0f + __expf(-z));
                yv *= z * sg;
                ygh[base + (size_t)u * DINNER] = __float2half_rn(yv);
            }
        }
        base   += 4 * DINNER;
        zidx   += 8 * DINNER;
        bcbase += 4 * DSTATE;
    }
}

// ---------------- launch ----------------
extern "C" void kernel_launch(void* const* d_in, const int* in_sizes, int n_in,
                              void* d_out, int out_size)
{
    const float* x       = (const float*)d_in[0];
    const float* norm_w  = (const float*)d_in[1];
    const float* norm_b  = (const float*)d_in[2];
    const float* W_in    = (const float*)d_in[3];
    const float* conv_w  = (const float*)d_in[4];
    const float* conv_b  = (const float*)d_in[5];
    const float* A_log   = (const float*)d_in[6];
    const float* W_b     = (const float*)d_in[7];
    const float* W_c     = (const float*)d_in[8];
    const float* W_delta = (const float*)d_in[9];
    const float* b_delta = (const float*)d_in[10];
    const float* D_param = (const float*)d_in[11];
    const float* W_out   = (const float*)d_in[12];
    float* out = (float*)d_out;

    __half *xnh, *xph, *ygh, *Wih, *Wdh, *Woh;
    float *xz, *xp, *dtb, *Bm, *Cm;
    cudaGetSymbolAddress((void**)&xnh, g_xn_h);
    cudaGetSymbolAddress((void**)&xz,  g_xz);
    cudaGetSymbolAddress((void**)&xp,  g_xp);
    cudaGetSymbolAddress((void**)&xph, g_xp_h);
    cudaGetSymbolAddress((void**)&dtb, g_dtb);
    cudaGetSymbolAddress((void**)&ygh, g_yg_h);
    cudaGetSymbolAddress((void**)&Bm,  g_Bm);
    cudaGetSymbolAddress((void**)&Cm,  g_Cm);
    cudaGetSymbolAddress((void**)&Wih, g_Wi_h);
    cudaGetSymbolAddress((void**)&Wdh, g_Wd_h);
    cudaGetSymbolAddress((void**)&Woh, g_Wo_h);

    cudaFuncSetAttribute(gemm_mma_kernel,
                         cudaFuncAttributeMaxDynamicSharedMemorySize, G_SMEM_BYTES);

    // weight transpose + fp16 convert
    wsplit_kernel<<<dim3(2 * DINNER / 32, DMODEL / 32), 256>>>(W_in, Wih, DMODEL, 2 * DINNER);
    wsplit_kernel<<<dim3(DINNER / 32, DINNER / 32), 256>>>(W_delta, Wdh, DINNER, DINNER);
    wsplit_kernel<<<dim3(DMODEL / 32, DINNER / 32), 256>>>(W_out, Woh, DINNER, DMODEL);

    // 1) layernorm -> xn fp16
    ln_kernel<<<NROWS, 256>>>(x, norm_w, norm_b, xnh);

    // 2) xz = xn @ W_in   [8192 x 4096, K=1024]
    gemm_mma_kernel<<<dim3(2 * DINNER / 128, NROWS / 128), 256, G_SMEM_BYTES>>>(
        xnh, Wih, xz, NROWS, 2 * DINNER, DMODEL, nullptr, nullptr, 0);

    // 3) conv + silu -> xp (fp32 + fp16)
    conv_silu_kernel<<<(NROWS * DINNER) / 256, 256>>>(xz, conv_w, conv_b, xp, xph);

    // 4) B, C projections
    bc_proj_kernel<<<NROWS / 16, 256>>>(xp, W_b, W_c, Bm, Cm);

    // 5) delta = softplus(xp @ W_delta + b_delta)   [8192 x 2048, K=2048]
    gemm_mma_kernel<<<dim3(DINNER / 128, NROWS / 128), 256, G_SMEM_BYTES>>>(
        xph, Wdh, dtb, NROWS, DINNER, DINNER, b_delta, nullptr, 1);

    // 6) selective scan + fused gate -> yg fp16
    scan_kernel<<<(B_SZ * DINNER) / 16, 64>>>(xp, dtb, Bm, Cm, A_log, D_param, xz, ygh);

    // 7) out = yg @ W_out + residual(x)   [8192 x 1024, K=2048]
    gemm_mma_kernel<<<dim3(DMODEL / 128, NROWS / 128), 256, G_SMEM_BYTES>>>(
        ygh, Woh, out, NROWS, DMODEL, DINNER, nullptr, x, 2);
}